// round 15
// baseline (speedup 1.0000x reference)
#include <cuda_runtime.h>
#include <cuda_fp16.h>
#include <cstdint>

#define OUT_F 4096
#define IN_F  4096
#define M_TOT 8192

#define BM 256
#define BN 256
#define KC 64                    // K halves per stage (128 bytes per row)
#define NKI (IN_F / KC)          // 64 k-iterations
#define STAGES 3
#define STAGE_BYTES 65536        // A 32KB (256 rows x 128B) + B 32KB
#define SMEM_STAGE0 1024
#define SMEM_SO_OFF (SMEM_STAGE0 + STAGES * STAGE_BYTES)   // 197632
#define SMEM_TOTAL (SMEM_SO_OFF + 32768)                   // 230400
#define NT 384                   // warps 0-7 producers; w8l0 fencer; w9l0 issuer; w8-11 epilogue

// idesc kind::f16: dtype=F32(1<<4), atype=FP16(0), btype=FP16(0), N/8<<17, M/16<<24
#define MMA_IDESC ((1u<<4) | ((BN/8u)<<17) | ((128u/16u)<<24))

// SW128 K-major smem descriptor base: layout=2, version=1, SBO=64, LBO=1
#define DESC_BASE ((2ull<<61) | (1ull<<46) | (64ull<<32) | (1ull<<16))
#define MAKE_DESC(a) (DESC_BASE | ((uint64_t)((a) >> 4) & 0x3FFF))

__device__ __half    g_X[(size_t)M_TOT * IN_F];          // x rounded to fp16 (64MB)
__device__ uint32_t  g_Wp[(size_t)OUT_F * IN_F / 8];     // nibble codes, [kt][n][c] (8.4MB)
__device__ __half2   g_SO[32 * OUT_F];                   // (scale, offset) per (khalf, n)

// ---------------------------------------------------------------- helpers
__device__ __forceinline__ uint32_t smem_u32(const void* p) {
    uint32_t a;
    asm("{ .reg .u64 t; cvta.to.shared.u64 t, %1; cvt.u32.u64 %0, t; }" : "=r"(a) : "l"(p));
    return a;
}
#define CP_ASYNC16(dst, src) \
    asm volatile("cp.async.cg.shared.global [%0], [%1], 16;" :: "r"(dst), "l"(src) : "memory")
#define CP_ASYNC_MBAR_ARRIVE(mb) \
    asm volatile("cp.async.mbarrier.arrive.noinc.shared.b64 [%0];" :: "r"(mb) : "memory")

#define MBARRIER_INIT(a, c) \
    asm volatile("mbarrier.init.shared.b64 [%0], %1;" :: "r"(a), "r"(c) : "memory")
#define MBARRIER_INVAL(a) \
    asm volatile("mbarrier.inval.shared.b64 [%0];" :: "r"(a) : "memory")
#define MBARRIER_ARRIVE(a) \
    asm volatile("mbarrier.arrive.release.cta.shared.b64 _, [%0];" :: "r"(a) : "memory")
#define MBARRIER_WAIT_PARITY(addr, par) do {                                   \
    uint32_t _m = (addr); uint32_t _p = (par); uint32_t _d;                    \
    asm volatile("{\n\t.reg .pred p;\n\t"                                      \
        "mbarrier.try_wait.parity.acquire.cta.shared::cta.b64 p, [%1], %2;\n\t"\
        "selp.b32 %0, 1, 0, p;\n\t}"                                           \
        : "=r"(_d) : "r"(_m), "r"(_p) : "memory");                             \
    if (!_d) {                                                                  \
        asm volatile("{\n\t.reg .pred P1;\n\t"                                 \
            "WL_%=:\n\t"                                                       \
            "mbarrier.try_wait.parity.acquire.cta.shared::cta.b64 P1, [%0], %1, 0x989680;\n\t" \
            "@P1 bra.uni WD_%=;\n\t"                                           \
            "bra.uni WL_%=;\n\t"                                               \
            "WD_%=:\n\t}"                                                      \
            :: "r"(_m), "r"(_p) : "memory");                                   \
    }                                                                           \
} while (0)

// ---------------------------------------------------------------- prepass
__global__ void prepass_kernel(const float* __restrict__ x,
                               const int* __restrict__ packed,
                               const float* __restrict__ scales,
                               const float* __restrict__ offsets) {
    if (blockIdx.x < 32768) {
        size_t i = (size_t)blockIdx.x * blockDim.x + threadIdx.x;  // float4 index
        float4 v = __ldcs(reinterpret_cast<const float4*>(x) + i);
        __half2 h0 = __floats2half2_rn(v.x, v.y);
        __half2 h1 = __floats2half2_rn(v.z, v.w);
        uint2 o;
        o.x = *reinterpret_cast<uint32_t*>(&h0);
        o.y = *reinterpret_cast<uint32_t*>(&h1);
        reinterpret_cast<uint2*>(g_X)[i] = o;
    } else if (blockIdx.x < 40960) {
        // word j holds codes c0..c7 (k-consecutive). byte t = c_t | c_{t+4}<<4 so
        // lo-nibbles = {c0..c3}, hi-nibbles = {c4..c7}. Layout stage-major [kt][n][c].
        int j = (blockIdx.x - 32768) * blockDim.x + threadIdx.x;
        int4 p = __ldcs(reinterpret_cast<const int4*>(packed) + j);
        const uint32_t c0 = (uint32_t)(p.x & 0xF),  c1 = (uint32_t)((p.x >> 4) & 0xF);
        const uint32_t c2 = (uint32_t)(p.y & 0xF),  c3 = (uint32_t)((p.y >> 4) & 0xF);
        const uint32_t c4 = (uint32_t)(p.z & 0xF),  c5 = (uint32_t)((p.z >> 4) & 0xF);
        const uint32_t c6 = (uint32_t)(p.w & 0xF),  c7 = (uint32_t)((p.w >> 4) & 0xF);
        const uint32_t w = (c0 | (c4 << 4)) | ((c1 | (c5 << 4)) << 8) |
                           ((c2 | (c6 << 4)) << 16) | ((c3 | (c7 << 4)) << 24);
        const int n  = j >> 9;
        const int wk = j & 511;
        const int kt = wk >> 3;
        const int c  = wk & 7;
        g_Wp[(size_t)kt * 32768 + (size_t)n * 8 + c] = w;
    } else {
        int g = (blockIdx.x - 40960) * blockDim.x + threadIdx.x;
        int n = g >> 5;
        int kh = g & 31;
        g_SO[kh * OUT_F + n] = __floats2half2_rn(scales[g], offsets[g]);
    }
}

// ---------------------------------------------------------------- arch gate
#if defined(__CUDA_ARCH_FEAT_SM103_ALL)
#define HAS_TCGEN05 1
#else
#define HAS_TCGEN05 0
#endif

#if HAS_TCGEN05
#define TCGEN05_ALLOC(sa, n) \
    asm volatile("tcgen05.alloc.cta_group::1.sync.aligned.shared::cta.b32 [%0], %1;" \
                 :: "r"(sa), "r"((uint32_t)(n)) : "memory")
#define TCGEN05_DEALLOC(t, n) \
    asm volatile("tcgen05.dealloc.cta_group::1.sync.aligned.b32 %0, %1;" :: "r"(t), "r"((uint32_t)(n)))
#define TCGEN05_RELINQUISH() \
    asm volatile("tcgen05.relinquish_alloc_permit.cta_group::1.sync.aligned;")
#define TCGEN05_COMMIT(mb) \
    asm volatile("tcgen05.commit.cta_group::1.mbarrier::arrive::one.shared::cluster.b64 [%0];" \
                 :: "r"(mb) : "memory")
#define TCGEN05_FENCE_AFTER() asm volatile("tcgen05.fence::after_thread_sync;" ::: "memory")
#define TCGEN05_FENCE_BEFORE() asm volatile("tcgen05.fence::before_thread_sync;" ::: "memory")
#define TCGEN05_WAIT_LD() asm volatile("tcgen05.wait::ld.sync.aligned;" ::: "memory")
#define FENCE_PROXY_ASYNC() asm volatile("fence.proxy.async.shared::cta;" ::: "memory")

#define LDTM_X32(r, a) \
    asm volatile("tcgen05.ld.sync.aligned.32x32b.x32.b32 "                     \
        "{%0,%1,%2,%3,%4,%5,%6,%7,%8,%9,%10,%11,%12,%13,%14,%15,"              \
        "%16,%17,%18,%19,%20,%21,%22,%23,%24,%25,%26,%27,%28,%29,%30,%31}, [%32];" \
        : "=r"((r)[0]), "=r"((r)[1]), "=r"((r)[2]), "=r"((r)[3]),              \
          "=r"((r)[4]), "=r"((r)[5]), "=r"((r)[6]), "=r"((r)[7]),              \
          "=r"((r)[8]), "=r"((r)[9]), "=r"((r)[10]), "=r"((r)[11]),            \
          "=r"((r)[12]), "=r"((r)[13]), "=r"((r)[14]), "=r"((r)[15]),          \
          "=r"((r)[16]), "=r"((r)[17]), "=r"((r)[18]), "=r"((r)[19]),          \
          "=r"((r)[20]), "=r"((r)[21]), "=r"((r)[22]), "=r"((r)[23]),          \
          "=r"((r)[24]), "=r"((r)[25]), "=r"((r)[26]), "=r"((r)[27]),          \
          "=r"((r)[28]), "=r"((r)[29]), "=r"((r)[30]), "=r"((r)[31])           \
        : "r"(a))

__device__ __forceinline__ void mma_f16_ss(uint32_t d, uint64_t ad, uint64_t bd,
                                           uint32_t idesc, uint32_t en) {
    asm volatile(
        "{\n\t.reg .pred p;\n\tsetp.ne.u32 p, %5, 0;\n\t"
        "tcgen05.mma.cta_group::1.kind::f16 [%0], %1, %2, %3, {%4,%4,%4,%4}, p;\n\t}"
        :: "r"(d), "l"(ad), "l"(bd), "r"(idesc), "r"(0u), "r"(en) : "memory");
}
#endif  // HAS_TCGEN05

// mbarrier layout (24B/stage): FULL (producers), FULLF (fencer), EMPTY; done at end
#define FULLB(sb, s)  ((sb) + 8 + (s) * 24)
#define FULLF(sb, s)  ((sb) + 16 + (s) * 24)
#define EMPTYB(sb, s) ((sb) + 24 + (s) * 24)
#define DONEB(sb)     ((sb) + 8 + STAGES * 24)

__global__ void __launch_bounds__(NT, 1)
gemm_tc(const float* __restrict__ bias, float* __restrict__ Y) {
#if HAS_TCGEN05
    extern __shared__ __align__(1024) char smem[];
    const uint32_t sb = smem_u32(smem);
    const int tid = threadIdx.x;
    const int wid = tid >> 5;
    const int lane = tid & 31;
    const int m0 = blockIdx.y * BM;
    const int n0 = blockIdx.x * BN;

    if (wid == 8) TCGEN05_ALLOC(sb, 512);
    if (tid == 0) {
#pragma unroll
        for (int s = 0; s < STAGES; s++) {
            MBARRIER_INIT(FULLB(sb, s), 512);   // 256 cp.async arrivals + 256 STS arrivals
            MBARRIER_INIT(FULLF(sb, s), 1);     // fencer arrives one
            MBARRIER_INIT(EMPTYB(sb, s), 1);    // tcgen05.commit arrives one
        }
        MBARRIER_INIT(DONEB(sb), 1);
    }
    // stage (scale, offset) half2 table for this CTA's 256 out-features (32KB)
    {
        __half2* so = reinterpret_cast<__half2*>(smem + SMEM_SO_OFF);
        for (int idx = tid; idx < 32 * 256; idx += NT) {
            const int kh = idx >> 8;
            const int r  = idx & 255;
            so[idx] = g_SO[kh * OUT_F + n0 + r];
        }
    }
    __syncthreads();
    uint32_t tmem;
    asm volatile("ld.shared.b32 %0, [%1];" : "=r"(tmem) : "r"(sb));

    if (wid < 8) {
        // ---------------- producers: warps 0-7 (256 threads) ----------------
        // B-code LDG prefetched TWO stages ahead: issue(kt+2)@top of kt ->
        // use mid kt+2 (~2.3 periods of cover >> worst-case L2 latency).
        const int row8 = tid >> 3;
        const int c    = tid & 7;
        const __half*   Xp = g_X + (size_t)m0 * IN_F;
        const uint32_t* Wp = g_Wp + (size_t)n0 * 8;   // + kt*32768 per stage
        const __half2*  so = reinterpret_cast<const __half2*>(smem + SMEM_SO_OFF);
        const __half2 k1024 = __halves2half2(__ushort_as_half(0x6400),
                                             __ushort_as_half(0x6400));
        uint32_t w0[8], w1[8], w2[8];
#pragma unroll
        for (int i = 0; i < 8; i++)
            w0[i] = Wp[(size_t)(i * 32 + row8) * 8 + c];
#pragma unroll
        for (int i = 0; i < 8; i++)
            w1[i] = Wp[32768 + (size_t)(i * 32 + row8) * 8 + c];
        for (int kt = 0; kt < NKI; kt++) {
            const int b = kt % STAGES;
            // ---- prefetch codes for kt+2 (issued before any waits) ----
            if (kt + 2 < NKI) {
                const uint32_t* Wn = Wp + (size_t)(kt + 2) * 32768;
#pragma unroll
                for (int i = 0; i < 8; i++)
                    w2[i] = Wn[(size_t)(i * 32 + row8) * 8 + c];
            }
            if (kt >= STAGES)
                MBARRIER_WAIT_PARITY(EMPTYB(sb, b), (uint32_t)((kt / STAGES + 1) & 1));
            const uint32_t abase = sb + SMEM_STAGE0 + b * STAGE_BYTES;
            const size_t ko = (size_t)kt * KC;
#pragma unroll
            for (int i = 0; i < 8; i++) {
                const int row = i * 32 + row8;
                const uint32_t sw = (uint32_t)(row * 128 + ((c ^ (row & 7)) << 4));
                CP_ASYNC16(abase + sw,
                           __cvta_generic_to_global(Xp + (size_t)row * IN_F + ko + c * 8));
            }
            CP_ASYNC_MBAR_ARRIVE(FULLB(sb, b));
            // ---- B: dequant codes loaded 2 iters ago, STS ----
            const int kh = kt >> 1;
#pragma unroll
            for (int i = 0; i < 8; i++) {
                const int row = i * 32 + row8;
                const __half2 sov = so[kh * 256 + row];   // broadcast LDS, hidden
                const __half2 s2 = __low2half2(sov);
                const __half2 o2 = __high2half2(sov);
                const uint32_t w = w0[i];
                const uint32_t lo = w & 0x0F0F0F0Fu;
                const uint32_t hi = (w >> 4) & 0x0F0F0F0Fu;
                uint32_t h[4];
#pragma unroll
                for (int j = 0; j < 2; j++) {
                    const uint32_t m = j ? hi : lo;
                    const uint32_t plo = __byte_perm(m, 0x64646464u, 0x4140);
                    const uint32_t phi = __byte_perm(m, 0x64646464u, 0x4342);
                    __half2 clo = __hsub2(*reinterpret_cast<const __half2*>(&plo), k1024);
                    __half2 chi = __hsub2(*reinterpret_cast<const __half2*>(&phi), k1024);
                    __half2 wlo = __hfma2(clo, s2, o2);
                    __half2 whi = __hfma2(chi, s2, o2);
                    h[2 * j + 0] = *reinterpret_cast<uint32_t*>(&wlo);
                    h[2 * j + 1] = *reinterpret_cast<uint32_t*>(&whi);
                }
                const uint32_t sw = (uint32_t)(row * 128 + ((c ^ (row & 7)) << 4));
                *reinterpret_cast<uint4*>(smem + SMEM_STAGE0 + b * STAGE_BYTES + 32768 + sw)
                    = make_uint4(h[0], h[1], h[2], h[3]);
            }
            MBARRIER_ARRIVE(FULLB(sb, b));     // release: publishes STS
#pragma unroll
            for (int i = 0; i < 8; i++) { w0[i] = w1[i]; w1[i] = w2[i]; }
        }
    } else if (tid == 256) {
        // ---------------- fencer: warp 8 lane 0 ----------------
        for (int kt = 0; kt < NKI; kt++) {
            const int b = kt % STAGES;
            MBARRIER_WAIT_PARITY(FULLB(sb, b), (uint32_t)((kt / STAGES) & 1));
            FENCE_PROXY_ASYNC();               // generic STS -> async proxy
            MBARRIER_ARRIVE(FULLF(sb, b));
        }
    } else if (tid == 288) {
        // ---------------- MMA issuer: warp 9 lane 0 ----------------
        for (int kt = 0; kt < NKI; kt++) {
            const int b = kt % STAGES;
            MBARRIER_WAIT_PARITY(FULLF(sb, b), (uint32_t)((kt / STAGES) & 1));
            const uint32_t ss = sb + SMEM_STAGE0 + b * STAGE_BYTES;
            const uint64_t a0 = MAKE_DESC(ss);
            const uint64_t a1 = MAKE_DESC(ss + 16384);
            const uint64_t bd = MAKE_DESC(ss + 32768);
#pragma unroll
            for (int ks = 0; ks < 4; ks++) {
                const uint32_t en = (kt > 0 || ks > 0) ? 1u : 0u;
                mma_f16_ss(tmem,       a0 + ks * 2, bd + ks * 2, MMA_IDESC, en);
                mma_f16_ss(tmem + 256, a1 + ks * 2, bd + ks * 2, MMA_IDESC, en);
            }
            TCGEN05_COMMIT(EMPTYB(sb, b));
        }
        TCGEN05_COMMIT(DONEB(sb));             // in-order: fires when ALL MMAs done
    }

    // ---------------- epilogue: warps 8-11 ----------------
    if (wid >= 8) {
        MBARRIER_WAIT_PARITY(DONEB(sb), 0u);
        TCGEN05_FENCE_AFTER();
        const int wid2 = wid - 8;
#pragma unroll
        for (int half = 0; half < 2; half++) {
            const int m = m0 + half * 128 + wid2 * 32 + lane;
            float* yrow = Y + (size_t)m * OUT_F + n0;
#pragma unroll
            for (int c0 = 0; c0 < 256; c0 += 32) {
                uint32_t r[32];
                LDTM_X32(r, tmem + half * 256 + c0);
                TCGEN05_WAIT_LD();
                const float* bp = bias + n0 + c0;
#pragma unroll
                for (int j = 0; j < 32; j += 4) {
                    float4 v;
                    v.x = __uint_as_float(r[j + 0]) + bp[j + 0];
                    v.y = __uint_as_float(r[j + 1]) + bp[j + 1];
                    v.z = __uint_as_float(r[j + 2]) + bp[j + 2];
                    v.w = __uint_as_float(r[j + 3]) + bp[j + 3];
                    *reinterpret_cast<float4*>(yrow + c0 + j) = v;
                }
            }
        }
        TCGEN05_FENCE_BEFORE();
    }

    __syncthreads();
    if (tid == 0) {
#pragma unroll
        for (int s = 0; s < STAGES; s++) {
            MBARRIER_INVAL(FULLB(sb, s));
            MBARRIER_INVAL(FULLF(sb, s));
            MBARRIER_INVAL(EMPTYB(sb, s));
        }
        MBARRIER_INVAL(DONEB(sb));
    }
    __syncthreads();
    if (wid == 8) {
        TCGEN05_RELINQUISH();
        TCGEN05_DEALLOC(tmem, 512);
    }
#endif  // HAS_TCGEN05
}

// ---------------------------------------------------------------- launch
extern "C" void kernel_launch(void* const* d_in, const int* in_sizes, int n_in,
                              void* d_out, int out_size) {
    const float* x       = (const float*)d_in[0];
    const int*   packed  = (const int*)d_in[1];
    const float* scales  = (const float*)d_in[2];
    const float* offsets = (const float*)d_in[3];
    const float* bias    = (const float*)d_in[4];
    float* out = (float*)d_out;

    // fused prepass: X fp16-round + PRMT-ready stage-major nibble repack + SO table
    prepass_kernel<<<41472, 256>>>(x, packed, scales, offsets);

    // main GEMM: 256x256 tiles, tcgen05 fp16, depth-2 prefetched in-producer dequant
    static bool attr_set = false;
    if (!attr_set) {
        cudaFuncSetAttribute(gemm_tc, cudaFuncAttributeMaxDynamicSharedMemorySize, SMEM_TOTAL);
        attr_set = true;
    }
    dim3 grid(OUT_F / BN, M_TOT / BM);   // (16, 32)
    gemm_tc<<<grid, NT, SMEM_TOTAL>>>(bias, out);
}

// round 16
// speedup vs baseline: 1.1557x; 1.1557x over previous
#include <cuda_runtime.h>
#include <cuda_fp16.h>
#include <cuda.h>
#include <cstdint>

#define OUT_F 4096
#define IN_F  4096
#define M_TOT 8192

#define BM 256
#define BN 256
#define KC 64                    // K halves per stage (128 bytes per row)
#define NKI (IN_F / KC)          // 64 k-iterations
#define STAGES 3
#define STAGE_BYTES 65536        // A 32KB (256 rows x 128B) + B 32KB
#define SMEM_STAGE0 1024
#define SMEM_TOTAL (SMEM_STAGE0 + STAGES * STAGE_BYTES)   // 197632
#define NT 128                   // w0l0 TMA producer, w1l0 MMA issuer, all 4 warps epilogue

// idesc kind::f16: dtype=F32(1<<4), atype=FP16(0), btype=FP16(0), N/8<<17, M/16<<24
#define MMA_IDESC ((1u<<4) | ((BN/8u)<<17) | ((128u/16u)<<24))

// SW128 K-major smem descriptor base: layout=2, version=1, SBO=64, LBO=1
#define DESC_BASE ((2ull<<61) | (1ull<<46) | (64ull<<32) | (1ull<<16))
#define MAKE_DESC(a) (DESC_BASE | ((uint64_t)((a) >> 4) & 0x3FFF))

__device__ __half g_W[(size_t)OUT_F * IN_F];   // dequantized fp16 (32MB)
__device__ __half g_X[(size_t)M_TOT * IN_F];   // x rounded to fp16 (64MB)

// ---------------------------------------------------------------- helpers
__device__ __forceinline__ uint32_t smem_u32(const void* p) {
    uint32_t a;
    asm("{ .reg .u64 t; cvta.to.shared.u64 t, %1; cvt.u32.u64 %0, t; }" : "=r"(a) : "l"(p));
    return a;
}
#define MBARRIER_INIT(a, c) \
    asm volatile("mbarrier.init.shared.b64 [%0], %1;" :: "r"(a), "r"(c) : "memory")
#define MBARRIER_INVAL(a) \
    asm volatile("mbarrier.inval.shared.b64 [%0];" :: "r"(a) : "memory")
#define MBARRIER_EXPECT_TX(a, b) \
    asm volatile("mbarrier.arrive.expect_tx.shared.b64 _, [%0], %1;" :: "r"(a), "r"((uint32_t)(b)) : "memory")
#define MBARRIER_WAIT_PARITY(addr, par) do {                                   \
    uint32_t _m = (addr); uint32_t _p = (par); uint32_t _d;                    \
    asm volatile("{\n\t.reg .pred p;\n\t"                                      \
        "mbarrier.try_wait.parity.acquire.cta.shared::cta.b64 p, [%1], %2;\n\t"\
        "selp.b32 %0, 1, 0, p;\n\t}"                                           \
        : "=r"(_d) : "r"(_m), "r"(_p) : "memory");                             \
    if (!_d) {                                                                  \
        asm volatile("{\n\t.reg .pred P1;\n\t"                                 \
            "WL_%=:\n\t"                                                       \
            "mbarrier.try_wait.parity.acquire.cta.shared::cta.b64 P1, [%0], %1, 0x989680;\n\t" \
            "@P1 bra.uni WD_%=;\n\t"                                           \
            "bra.uni WL_%=;\n\t"                                               \
            "WD_%=:\n\t}"                                                      \
            :: "r"(_m), "r"(_p) : "memory");                                   \
    }                                                                           \
} while (0)

// ---------------------------------------------------------------- prepass (R14, proven)
__global__ void prepass_kernel(const float* __restrict__ x,
                               const int* __restrict__ packed,
                               const float* __restrict__ scales,
                               const float* __restrict__ offsets) {
    if (blockIdx.x < 32768) {
        size_t i = (size_t)blockIdx.x * blockDim.x + threadIdx.x;  // float4 index
        float4 v = __ldcs(reinterpret_cast<const float4*>(x) + i); // streaming read
        __half2 h0 = __floats2half2_rn(v.x, v.y);
        __half2 h1 = __floats2half2_rn(v.z, v.w);
        uint2 o;
        o.x = *reinterpret_cast<uint32_t*>(&h0);
        o.y = *reinterpret_cast<uint32_t*>(&h1);
        reinterpret_cast<uint2*>(g_X)[i] = o;
    } else {
        // thread j: packed[4j..4j+3] -> 8 codes -> 8 fp16 weights (one 16B store)
        size_t j = (size_t)(blockIdx.x - 32768) * blockDim.x + threadIdx.x;
        int4 p = __ldcs(reinterpret_cast<const int4*>(packed) + j);
        const int g = (int)(j >> 4);
        const float s = scales[g];
        const float o = offsets[g];
        __half2 h0 = __floats2half2_rn(fmaf((float)(p.x & 0xF), s, o),
                                       fmaf((float)((p.x >> 4) & 0xF), s, o));
        __half2 h1 = __floats2half2_rn(fmaf((float)(p.y & 0xF), s, o),
                                       fmaf((float)((p.y >> 4) & 0xF), s, o));
        __half2 h2 = __floats2half2_rn(fmaf((float)(p.z & 0xF), s, o),
                                       fmaf((float)((p.z >> 4) & 0xF), s, o));
        __half2 h3 = __floats2half2_rn(fmaf((float)(p.w & 0xF), s, o),
                                       fmaf((float)((p.w >> 4) & 0xF), s, o));
        uint4 out;
        out.x = *reinterpret_cast<uint32_t*>(&h0);
        out.y = *reinterpret_cast<uint32_t*>(&h1);
        out.z = *reinterpret_cast<uint32_t*>(&h2);
        out.w = *reinterpret_cast<uint32_t*>(&h3);
        reinterpret_cast<uint4*>(g_W)[j] = out;
    }
}

// ---------------------------------------------------------------- arch gate
#if defined(__CUDA_ARCH_FEAT_SM103_ALL)
#define HAS_TCGEN05 1
#else
#define HAS_TCGEN05 0
#endif

#if HAS_TCGEN05
#define TCGEN05_ALLOC(sa, n) \
    asm volatile("tcgen05.alloc.cta_group::1.sync.aligned.shared::cta.b32 [%0], %1;" \
                 :: "r"(sa), "r"((uint32_t)(n)) : "memory")
#define TCGEN05_DEALLOC(t, n) \
    asm volatile("tcgen05.dealloc.cta_group::1.sync.aligned.b32 %0, %1;" :: "r"(t), "r"((uint32_t)(n)))
#define TCGEN05_RELINQUISH() \
    asm volatile("tcgen05.relinquish_alloc_permit.cta_group::1.sync.aligned;")
#define TCGEN05_COMMIT(mb) \
    asm volatile("tcgen05.commit.cta_group::1.mbarrier::arrive::one.shared::cluster.b64 [%0];" \
                 :: "r"(mb) : "memory")
#define TCGEN05_FENCE_AFTER() asm volatile("tcgen05.fence::after_thread_sync;" ::: "memory")
#define TCGEN05_FENCE_BEFORE() asm volatile("tcgen05.fence::before_thread_sync;" ::: "memory")
#define TCGEN05_WAIT_LD() asm volatile("tcgen05.wait::ld.sync.aligned;" ::: "memory")

#define TMA_LOAD_2D(dst, map, cx, cy, mb) \
    asm volatile("cp.async.bulk.tensor.2d.shared::cta.global.tile.mbarrier::complete_tx::bytes " \
        "[%0], [%1, {%2, %3}], [%4];" \
        :: "r"(dst), "l"(map), "r"(cx), "r"(cy), "r"(mb) : "memory")

#define LDTM_X32(r, a) \
    asm volatile("tcgen05.ld.sync.aligned.32x32b.x32.b32 "                     \
        "{%0,%1,%2,%3,%4,%5,%6,%7,%8,%9,%10,%11,%12,%13,%14,%15,"              \
        "%16,%17,%18,%19,%20,%21,%22,%23,%24,%25,%26,%27,%28,%29,%30,%31}, [%32];" \
        : "=r"((r)[0]), "=r"((r)[1]), "=r"((r)[2]), "=r"((r)[3]),              \
          "=r"((r)[4]), "=r"((r)[5]), "=r"((r)[6]), "=r"((r)[7]),              \
          "=r"((r)[8]), "=r"((r)[9]), "=r"((r)[10]), "=r"((r)[11]),            \
          "=r"((r)[12]), "=r"((r)[13]), "=r"((r)[14]), "=r"((r)[15]),          \
          "=r"((r)[16]), "=r"((r)[17]), "=r"((r)[18]), "=r"((r)[19]),          \
          "=r"((r)[20]), "=r"((r)[21]), "=r"((r)[22]), "=r"((r)[23]),          \
          "=r"((r)[24]), "=r"((r)[25]), "=r"((r)[26]), "=r"((r)[27]),          \
          "=r"((r)[28]), "=r"((r)[29]), "=r"((r)[30]), "=r"((r)[31])           \
        : "r"(a))

__device__ __forceinline__ void mma_f16_ss(uint32_t d, uint64_t ad, uint64_t bd,
                                           uint32_t idesc, uint32_t en) {
    asm volatile(
        "{\n\t.reg .pred p;\n\tsetp.ne.u32 p, %5, 0;\n\t"
        "tcgen05.mma.cta_group::1.kind::f16 [%0], %1, %2, %3, {%4,%4,%4,%4}, p;\n\t}"
        :: "r"(d), "l"(ad), "l"(bd), "r"(idesc), "r"(0u), "r"(en) : "memory");
}
#endif  // HAS_TCGEN05

// mbarrier layout: full[s] at sb+8+s*16, empty[s] at sb+16+s*16, done at sb+8+S*16
#define FULLB(sb, s)  ((sb) + 8 + (s) * 16)
#define EMPTYB(sb, s) ((sb) + 16 + (s) * 16)
#define DONEB(sb)     ((sb) + 8 + STAGES * 16)

__global__ void __launch_bounds__(NT, 1)
gemm_tc(const __grid_constant__ CUtensorMap tmx,
        const __grid_constant__ CUtensorMap tmw,
        const float* __restrict__ bias, float* __restrict__ Y) {
#if HAS_TCGEN05
    extern __shared__ __align__(1024) char smem[];
    const uint32_t sb = smem_u32(smem);
    const int tid = threadIdx.x;
    const int wid = tid >> 5;
    const int lane = tid & 31;
    const int m0 = blockIdx.y * BM;
    const int n0 = blockIdx.x * BN;

    if (wid == 0) TCGEN05_ALLOC(sb, 512);
    if (tid == 0) {
#pragma unroll
        for (int s = 0; s < STAGES; s++) {
            MBARRIER_INIT(FULLB(sb, s), 1);     // expect_tx arrival only
            MBARRIER_INIT(EMPTYB(sb, s), 1);    // tcgen05.commit arrives one
        }
        MBARRIER_INIT(DONEB(sb), 1);
    }
    __syncthreads();
    uint32_t tmem;
    asm volatile("ld.shared.b32 %0, [%1];" : "=r"(tmem) : "r"(sb));

    if (tid == 0) {
        // ---------------- TMA producer: warp 0 lane 0 ----------------
        // Decoupled from the MMA issuer so the empty-wait never blocks MMA issue.
        for (int kt = 0; kt < NKI; kt++) {
            const int b = kt % STAGES;
            if (kt >= STAGES)
                MBARRIER_WAIT_PARITY(EMPTYB(sb, b), (uint32_t)((kt / STAGES + 1) & 1));
            const uint32_t abase = sb + SMEM_STAGE0 + b * STAGE_BYTES;
            const uint32_t bbase = abase + 32768;
            MBARRIER_EXPECT_TX(FULLB(sb, b), STAGE_BYTES);
            TMA_LOAD_2D(abase, &tmx, kt * KC, m0, FULLB(sb, b));   // A: 256 rows, 32KB
            TMA_LOAD_2D(bbase, &tmw, kt * KC, n0, FULLB(sb, b));   // B: 256 rows, 32KB
        }
    } else if (tid == 32) {
        // ---------------- MMA issuer: warp 1 lane 0 ----------------
        // TMA data is async-proxy; mbarrier complete_tx orders it for tcgen05.
        for (int kt = 0; kt < NKI; kt++) {
            const int b = kt % STAGES;
            MBARRIER_WAIT_PARITY(FULLB(sb, b), (uint32_t)((kt / STAGES) & 1));
            const uint32_t ss = sb + SMEM_STAGE0 + b * STAGE_BYTES;
            const uint64_t a0 = MAKE_DESC(ss);
            const uint64_t a1 = MAKE_DESC(ss + 16384);   // A rows 128-255
            const uint64_t bd = MAKE_DESC(ss + 32768);
#pragma unroll
            for (int ks = 0; ks < 4; ks++) {             // 4 x K=16 within 128B row
                const uint32_t en = (kt > 0 || ks > 0) ? 1u : 0u;
                mma_f16_ss(tmem,       a0 + ks * 2, bd + ks * 2, MMA_IDESC, en);
                mma_f16_ss(tmem + 256, a1 + ks * 2, bd + ks * 2, MMA_IDESC, en);
            }
            TCGEN05_COMMIT(EMPTYB(sb, b));               // frees buffer b for producer
        }
        TCGEN05_COMMIT(DONEB(sb));                       // in-order: fires when ALL MMAs done
    }

    // ---------------- epilogue: all 4 warps ----------------
    MBARRIER_WAIT_PARITY(DONEB(sb), 0u);
    TCGEN05_FENCE_AFTER();
#pragma unroll
    for (int half = 0; half < 2; half++) {
        const int m = m0 + half * 128 + wid * 32 + lane;
        float* yrow = Y + (size_t)m * OUT_F + n0;
#pragma unroll
        for (int c0 = 0; c0 < 256; c0 += 32) {
            uint32_t r[32];
            LDTM_X32(r, tmem + half * 256 + c0);
            TCGEN05_WAIT_LD();
            const float* bp = bias + n0 + c0;
#pragma unroll
            for (int j = 0; j < 32; j += 4) {
                float4 v;
                v.x = __uint_as_float(r[j + 0]) + bp[j + 0];
                v.y = __uint_as_float(r[j + 1]) + bp[j + 1];
                v.z = __uint_as_float(r[j + 2]) + bp[j + 2];
                v.w = __uint_as_float(r[j + 3]) + bp[j + 3];
                *reinterpret_cast<float4*>(yrow + c0 + j) = v;
            }
        }
    }
    TCGEN05_FENCE_BEFORE();

    __syncthreads();
    if (tid == 0) {
#pragma unroll
        for (int s = 0; s < STAGES; s++) {
            MBARRIER_INVAL(FULLB(sb, s));
            MBARRIER_INVAL(EMPTYB(sb, s));
        }
        MBARRIER_INVAL(DONEB(sb));
    }
    __syncthreads();
    if (wid == 0) {
        TCGEN05_RELINQUISH();
        TCGEN05_DEALLOC(tmem, 512);
    }
#endif  // HAS_TCGEN05
}

// ---------------------------------------------------------------- launch
typedef CUresult (*tmap_encode_fn)(
    CUtensorMap*, CUtensorMapDataType, cuuint32_t, void*,
    const cuuint64_t*, const cuuint64_t*, const cuuint32_t*, const cuuint32_t*,
    CUtensorMapInterleave, CUtensorMapSwizzle, CUtensorMapL2promotion,
    CUtensorMapFloatOOBfill);

extern "C" void kernel_launch(void* const* d_in, const int* in_sizes, int n_in,
                              void* d_out, int out_size) {
    const float* x       = (const float*)d_in[0];
    const int*   packed  = (const int*)d_in[1];
    const float* scales  = (const float*)d_in[2];
    const float* offsets = (const float*)d_in[3];
    const float* bias    = (const float*)d_in[4];
    float* out = (float*)d_out;

    static CUtensorMap tmx, tmw;
    static bool inited = false;
    if (!inited) {
        void* fn = nullptr;
        cudaDriverEntryPointQueryResult qr;
        cudaGetDriverEntryPointByVersion("cuTensorMapEncodeTiled", &fn, 12050,
                                         cudaEnableDefault, &qr);
        tmap_encode_fn enc = (tmap_encode_fn)fn;
        void *px = nullptr, *pw = nullptr;
        cudaGetSymbolAddress(&px, g_X);
        cudaGetSymbolAddress(&pw, g_W);

        cuuint64_t dimsx[2] = {IN_F, M_TOT};
        cuuint64_t strdx[1] = {IN_F * sizeof(__half)};
        cuuint32_t box[2]   = {KC, 256};          // 128B x 256 rows = 32KB
        cuuint32_t es[2]    = {1, 1};
        enc(&tmx, CU_TENSOR_MAP_DATA_TYPE_FLOAT16, 2, px, dimsx, strdx, box, es,
            CU_TENSOR_MAP_INTERLEAVE_NONE, CU_TENSOR_MAP_SWIZZLE_128B,
            CU_TENSOR_MAP_L2_PROMOTION_L2_128B, CU_TENSOR_MAP_FLOAT_OOB_FILL_NONE);

        cuuint64_t dimsw[2] = {IN_F, OUT_F};
        cuuint64_t strdw[1] = {IN_F * sizeof(__half)};
        enc(&tmw, CU_TENSOR_MAP_DATA_TYPE_FLOAT16, 2, pw, dimsw, strdw, box, es,
            CU_TENSOR_MAP_INTERLEAVE_NONE, CU_TENSOR_MAP_SWIZZLE_128B,
            CU_TENSOR_MAP_L2_PROMOTION_L2_128B, CU_TENSOR_MAP_FLOAT_OOB_FILL_NONE);

        cudaFuncSetAttribute(gemm_tc, cudaFuncAttributeMaxDynamicSharedMemorySize,
                             SMEM_TOTAL);
        inited = true;
    }

    // fused prepass v2 (R14): X fp16-round + vectorized W dequant
    prepass_kernel<<<40960, 256>>>(x, packed, scales, offsets);

    // main GEMM: 256x256 tiles, tcgen05 fp16, single-thread TMA producer
    dim3 grid(OUT_F / BN, M_TOT / BM);   // (16, 32)
    gemm_tc<<<grid, NT, SMEM_TOTAL>>>(tmx, tmw, bias, out);
}